// round 12
// baseline (speedup 1.0000x reference)
#include <cuda_runtime.h>
#include <math.h>

// R11: per-step persistent dataflow kernel. Numerics byte-identical to R10
// (serial ascending-k fp32 FMA chain per output, post-sum bias, de-fused
// gates, reference-ordered log-softmax). One launch per step; 296 resident
// blocks consume a work queue of GEMM tiles + fused gate chunks + fused
// W_out+softmax units, with counter-based dependency tracking.

// Problem constants
#define B     2048
#define L     256
#define H     1024
#define D     256
#define NSTEP 64
#define G3H   (3*H)   // 3072
#define KIN   (D + L) // 512

#define NBLK  296     // 2 CTAs/SM x 148 SMs
#define TPB   256
#define UNITS 1600    // 4*384 GEMM tiles + 64 wout units

// ---------------- scratch (device globals: allocation-free) ----------------
__device__ float g_inp[(size_t)B * KIN];
__device__ float g_gi [(size_t)B * G3H];
__device__ float g_gh [(size_t)B * G3H];
__device__ float g_h1 [2 * (size_t)B * H];   // parity double-buffer
__device__ float g_h2 [2 * (size_t)B * H];

// dependency counters (monotonic across steps within one kernel_launch)
__device__ unsigned g_c1 [16 * 8];   // gate1 chunk counters (by, jx)
__device__ unsigned g_c2 [16 * 8];   // gate2 chunk counters
__device__ unsigned g_h1c[16];       // h1 slab ready (per by)
__device__ unsigned g_h2c[16];       // h2 slab ready
__device__ unsigned g_q  [NSTEP];    // per-step work queues

// shared memory layout (union via raw buffer)
struct SmemGemm { float As[2][16][132]; float Bs[2][16][132]; };  // 33792 B
struct SmemWout { float As[16][36];     float Bs[16][260];    };  // 18944 B
#define SMEM_BYTES 33792

// no-op: aligns ncu's -s 5 skip onto step_kernel(t=0)
__global__ void dummy_kernel() {}

__global__ void zero_kernel()
{
    int i = blockIdx.x * blockDim.x + threadIdx.x;
    if      (i < 128)          g_c1 [i]       = 0;
    else if (i < 256)          g_c2 [i - 128] = 0;
    else if (i < 272)          g_h1c[i - 256] = 0;
    else if (i < 288)          g_h2c[i - 272] = 0;
    else if (i < 288 + NSTEP)  g_q  [i - 288] = 0;
}

// ============ 128x128 GEMM tile (R10 body, byte-identical chain) ===========
__device__ __noinline__ void gemm_tile(char* smemraw,
    const float* __restrict__ A, int lda,
    const float* __restrict__ W, int ldw,
    const float* __restrict__ bias,
    float* __restrict__ C, int K, int m0, int n0)
{
    SmemGemm& sh = *reinterpret_cast<SmemGemm*>(smemraw);
    const int tid = threadIdx.x;
    const int tx  = tid & 15;
    const int ty  = tid >> 4;
    const int r0  = tid >> 2;
    const int c4  = tid & 3;

    const float* Ap = A + (size_t)(m0 + r0) * lda + c4 * 4;
    const float* Wp = W + (size_t)(n0 + r0) * ldw + c4 * 4;

    float acc[8][8];
    #pragma unroll
    for (int i = 0; i < 8; i++)
        #pragma unroll
        for (int j = 0; j < 8; j++) acc[i][j] = 0.f;

    float4 pa[2], pb[2];
    int cur = 0;

    auto fetchA = [&](int kt) {
        pa[0] = *reinterpret_cast<const float4*>(Ap + kt);
        pa[1] = *reinterpret_cast<const float4*>(Ap + (size_t)64 * lda + kt);
    };
    auto fetchB = [&](int kt) {
        pb[0] = *reinterpret_cast<const float4*>(Wp + kt);
        pb[1] = *reinterpret_cast<const float4*>(Wp + (size_t)64 * ldw + kt);
    };
    auto storeA = [&](int buf) {
        sh.As[buf][c4*4+0][r0] = pa[0].x; sh.As[buf][c4*4+1][r0] = pa[0].y;
        sh.As[buf][c4*4+2][r0] = pa[0].z; sh.As[buf][c4*4+3][r0] = pa[0].w;
        sh.As[buf][c4*4+0][r0+64] = pa[1].x; sh.As[buf][c4*4+1][r0+64] = pa[1].y;
        sh.As[buf][c4*4+2][r0+64] = pa[1].z; sh.As[buf][c4*4+3][r0+64] = pa[1].w;
    };
    auto storeB = [&](int buf) {
        sh.Bs[buf][c4*4+0][r0] = pb[0].x; sh.Bs[buf][c4*4+1][r0] = pb[0].y;
        sh.Bs[buf][c4*4+2][r0] = pb[0].z; sh.Bs[buf][c4*4+3][r0] = pb[0].w;
        sh.Bs[buf][c4*4+0][r0+64] = pb[1].x; sh.Bs[buf][c4*4+1][r0+64] = pb[1].y;
        sh.Bs[buf][c4*4+2][r0+64] = pb[1].z; sh.Bs[buf][c4*4+3][r0+64] = pb[1].w;
    };

    float a_fr[2][8], b_fr[2][8];
    auto load_frag = [&](int k, int s) {
        float4 a0 = *reinterpret_cast<const float4*>(&sh.As[cur][k][ty * 4]);
        float4 a1 = *reinterpret_cast<const float4*>(&sh.As[cur][k][64 + ty * 4]);
        float4 b0 = *reinterpret_cast<const float4*>(&sh.Bs[cur][k][tx * 4]);
        float4 b1 = *reinterpret_cast<const float4*>(&sh.Bs[cur][k][64 + tx * 4]);
        a_fr[s][0]=a0.x; a_fr[s][1]=a0.y; a_fr[s][2]=a0.z; a_fr[s][3]=a0.w;
        a_fr[s][4]=a1.x; a_fr[s][5]=a1.y; a_fr[s][6]=a1.z; a_fr[s][7]=a1.w;
        b_fr[s][0]=b0.x; b_fr[s][1]=b0.y; b_fr[s][2]=b0.z; b_fr[s][3]=b0.w;
        b_fr[s][4]=b1.x; b_fr[s][5]=b1.y; b_fr[s][6]=b1.z; b_fr[s][7]=b1.w;
    };

    const int ntiles = K / 16;
    fetchA(0); fetchB(0);
    storeA(0); storeB(0);
    __syncthreads();

    for (int t = 0; t < ntiles; t++) {
        const bool hn = (t + 1 < ntiles);
        if (hn) { fetchA((t + 1) * 16); fetchB((t + 1) * 16); }

        load_frag(0, 0);
        #pragma unroll
        for (int k = 0; k < 16; k++) {
            const int s = k & 1;
            if (k + 1 < 16) load_frag(k + 1, s ^ 1);
            if (k == 9  && hn) storeA(cur ^ 1);
            if (k == 13 && hn) storeB(cur ^ 1);
            #pragma unroll
            for (int i = 0; i < 8; i++)
                #pragma unroll
                for (int j = 0; j < 8; j++)
                    acc[i][j] = fmaf(a_fr[s][i], b_fr[s][j], acc[i][j]);
        }
        __syncthreads();
        if (hn) cur ^= 1;
    }

    float4 bb0 = *reinterpret_cast<const float4*>(bias + n0 + tx * 4);
    float4 bb1 = *reinterpret_cast<const float4*>(bias + n0 + 64 + tx * 4);

    #pragma unroll
    for (int i = 0; i < 8; i++) {
        int m = m0 + ((i < 4) ? (ty * 4 + i) : (64 + ty * 4 + (i - 4)));
        size_t off = (size_t)m * G3H + n0;
        float4 v0 = make_float4(__fadd_rn(acc[i][0], bb0.x),
                                __fadd_rn(acc[i][1], bb0.y),
                                __fadd_rn(acc[i][2], bb0.z),
                                __fadd_rn(acc[i][3], bb0.w));
        float4 v1 = make_float4(__fadd_rn(acc[i][4], bb1.x),
                                __fadd_rn(acc[i][5], bb1.y),
                                __fadd_rn(acc[i][6], bb1.z),
                                __fadd_rn(acc[i][7], bb1.w));
        *reinterpret_cast<float4*>(C + off + tx * 4)      = v0;
        *reinterpret_cast<float4*>(C + off + 64 + tx * 4) = v1;
    }
}

// ============ 128x128 GRU gate chunk (same formulas as R10) ================
__device__ __noinline__ void gate_chunk(
    const float* __restrict__ gi, const float* __restrict__ gh,
    const float* __restrict__ hprev, float* __restrict__ hout,
    int by, int jx)
{
    const int tid = threadIdx.x;
    const int cc  = (tid & 31) * 4;   // col chunk (coalesced within warp)
    const int r8  = tid >> 5;         // 0..7
    const int b0  = by * 128;
    const int jb  = jx * 128;

    for (int i = 0; i < 16; i++) {
        int row = b0 + r8 + i * 8;
        int j   = jb + cc;
        size_t gb = (size_t)row * G3H + j;
        size_t hb = (size_t)row * H + j;
        float4 ir4 = *reinterpret_cast<const float4*>(gi + gb);
        float4 iz4 = *reinterpret_cast<const float4*>(gi + gb + H);
        float4 in4 = *reinterpret_cast<const float4*>(gi + gb + 2 * H);
        float4 hr4 = *reinterpret_cast<const float4*>(gh + gb);
        float4 hz4 = *reinterpret_cast<const float4*>(gh + gb + H);
        float4 hn4 = *reinterpret_cast<const float4*>(gh + gb + 2 * H);
        float4 hp4 = *reinterpret_cast<const float4*>(hprev + hb);

        float hv[4];
        const float ir[4] = {ir4.x, ir4.y, ir4.z, ir4.w};
        const float iz[4] = {iz4.x, iz4.y, iz4.z, iz4.w};
        const float in_[4] = {in4.x, in4.y, in4.z, in4.w};
        const float hr[4] = {hr4.x, hr4.y, hr4.z, hr4.w};
        const float hz[4] = {hz4.x, hz4.y, hz4.z, hz4.w};
        const float hn[4] = {hn4.x, hn4.y, hn4.z, hn4.w};
        const float hp[4] = {hp4.x, hp4.y, hp4.z, hp4.w};
        #pragma unroll
        for (int e = 0; e < 4; e++) {
            float sr = __fadd_rn(ir[e], hr[e]);
            float sz = __fadd_rn(iz[e], hz[e]);
            float r  = __fdiv_rn(1.f, __fadd_rn(1.f, expf(-sr)));
            float zg = __fdiv_rn(1.f, __fadd_rn(1.f, expf(-sz)));
            float n  = tanhf(__fadd_rn(in_[e], __fmul_rn(r, hn[e])));
            hv[e] = __fadd_rn(__fmul_rn(__fsub_rn(1.f, zg), n),
                              __fmul_rn(zg, hp[e]));
        }
        *reinterpret_cast<float4*>(hout + hb) =
            make_float4(hv[0], hv[1], hv[2], hv[3]);
    }
}

// ============ W_out (32x256, K=1024) + fused log-softmax/argmax ============
__device__ __noinline__ void wout_unit(char* smemraw,
    const float* __restrict__ A,      // h2 current
    const float* __restrict__ Wo, const float* __restrict__ bo,
    float* __restrict__ dout, float* __restrict__ inp,
    int m0, int t)
{
    SmemWout& sh = *reinterpret_cast<SmemWout*>(smemraw);
    const int tid = threadIdx.x;
    const int tx  = tid & 63;     // 64 x 4 = 256 cols
    const int ty  = tid >> 6;     // 4 x 8 = 32 rows

    float acc[8][4];
    #pragma unroll
    for (int i = 0; i < 8; i++)
        #pragma unroll
        for (int j = 0; j < 4; j++) acc[i][j] = 0.f;

    for (int kt = 0; kt < H; kt += 16) {
        if (tid < 128) {
            int r = tid >> 2, c4 = tid & 3;
            float4 v = *reinterpret_cast<const float4*>(
                A + (size_t)(m0 + r) * H + kt + c4 * 4);
            sh.As[c4*4+0][r] = v.x; sh.As[c4*4+1][r] = v.y;
            sh.As[c4*4+2][r] = v.z; sh.As[c4*4+3][r] = v.w;
        }
        #pragma unroll
        for (int l = 0; l < 4; l++) {
            int idx = tid + l * 256;
            int r = idx >> 2, c4 = idx & 3;
            float4 v = *reinterpret_cast<const float4*>(
                Wo + (size_t)r * H + kt + c4 * 4);
            sh.Bs[c4*4+0][r] = v.x; sh.Bs[c4*4+1][r] = v.y;
            sh.Bs[c4*4+2][r] = v.z; sh.Bs[c4*4+3][r] = v.w;
        }
        __syncthreads();

        #pragma unroll
        for (int k = 0; k < 16; k++) {
            float a[8];
            #pragma unroll
            for (int i = 0; i < 8; i++) a[i] = sh.As[k][ty * 8 + i];
            float4 b = *reinterpret_cast<const float4*>(&sh.Bs[k][tx * 4]);
            float bv[4] = {b.x, b.y, b.z, b.w};
            #pragma unroll
            for (int i = 0; i < 8; i++)
                #pragma unroll
                for (int j = 0; j < 4; j++)
                    acc[i][j] = fmaf(a[i], bv[j], acc[i][j]);
        }
        __syncthreads();
    }

    // bias then park logits in smem (reuse buffer; all tile reads done)
    float* sm = reinterpret_cast<float*>(smemraw);   // 32 x 256
    float4 b4 = *reinterpret_cast<const float4*>(bo + tx * 4);
    const float bb[4] = {b4.x, b4.y, b4.z, b4.w};
    #pragma unroll
    for (int i = 0; i < 8; i++) {
        int row = ty * 8 + i;
        #pragma unroll
        for (int j = 0; j < 4; j++)
            sm[row * 256 + tx * 4 + j] = __fadd_rn(acc[i][j], bb[j]);
    }
    __syncthreads();

    // paired log-softmax + argmax + one-hot (reference order)
    for (int i = 0; i < 16; i++) {
        int p = i * 256 + tid;            // 4096 pairs
        int r = p >> 7;
        int f = p & 127;
        float a = sm[r * 256 + f];
        float c = sm[r * 256 + 128 + f];
        float m  = fmaxf(a, c);
        float sa = __fsub_rn(a, m);
        float sc = __fsub_rn(c, m);
        float lse = logf(__fadd_rn(expf(sa), expf(sc)));
        float la = __fsub_rn(sa, lse);
        float lc = __fsub_rn(sc, lse);
        int b_ = m0 + r;
        size_t ob = (size_t)b_ * NSTEP * D + (size_t)t * D;
        dout[ob + f]       = la;
        dout[ob + 128 + f] = lc;
        int idx = (la >= lc) ? 0 : 1;
        inp[(size_t)b_ * KIN + 2 * f]     = (idx == 0) ? 1.f : 0.f;
        inp[(size_t)b_ * KIN + 2 * f + 1] = (idx == 1) ? 1.f : 0.f;
    }
}

// ============ persistent per-step kernel ===================================
__global__ void __launch_bounds__(TPB, 2) step_kernel(
    const float* __restrict__ Wih1, const float* __restrict__ bih1,
    const float* __restrict__ Whh1, const float* __restrict__ bhh1,
    const float* __restrict__ Wih2, const float* __restrict__ bih2,
    const float* __restrict__ Whh2, const float* __restrict__ bhh2,
    const float* __restrict__ Wo,   const float* __restrict__ bo,
    float* __restrict__ dout, int t)
{
    __shared__ __align__(16) char smem[SMEM_BYTES];
    __shared__ unsigned s_u, s_old;

    const int cur = t & 1, prv = cur ^ 1;
    float* h1c_ = g_h1 + (size_t)cur * B * H;
    float* h1p  = g_h1 + (size_t)prv * B * H;
    float* h2c_ = g_h2 + (size_t)cur * B * H;
    float* h2p  = g_h2 + (size_t)prv * B * H;
    const unsigned tgt6 = 6u * (t + 1);
    const unsigned tgt8 = 8u * (t + 1);

    for (;;) {
        if (threadIdx.x == 0) s_u = atomicAdd(&g_q[t], 1u);
        __syncthreads();
        unsigned u = s_u;
        if (u >= UNITS) break;

        if (u < 1536u) {
            unsigned seg = u / 384u, v = u % 384u;
            int nx = (int)(v % 24u), by = (int)(v / 24u);
            const bool layer2 = (seg >= 2);

            if (layer2) {      // gi2/gh2 need h1 slab (and gate1 done w/ gi/gh[by])
                if (threadIdx.x == 0) {
                    while (*(volatile unsigned*)&g_h1c[by] < tgt8) {}
                    __threadfence();
                }
                __syncthreads();
            }
            const float *A, *W, *bias; float* Cd; int lda, ldw, K;
            if (seg == 0)      { A=h1p;   lda=H;   W=Whh1; ldw=H;   bias=bhh1; Cd=g_gh; K=H;   }
            else if (seg == 1) { A=g_inp; lda=KIN; W=Wih1; ldw=KIN; bias=bih1; Cd=g_gi; K=KIN; }
            else if (seg == 2) { A=h1c_;  lda=H;   W=Wih2; ldw=H;   bias=bih2; Cd=g_gi; K=H;   }
            else               { A=(t==0 ? h1c_ : h2p);
                                 lda=H;   W=Whh2; ldw=H;   bias=bhh2; Cd=g_gh; K=H;   }

            gemm_tile(smem, A, lda, W, ldw, bias, Cd, K, by * 128, nx * 128);

            __threadfence();
            __syncthreads();
            unsigned* ctr = layer2 ? &g_c2[by * 8 + (nx & 7)]
                                   : &g_c1[by * 8 + (nx & 7)];
            if (threadIdx.x == 0) s_old = atomicAdd(ctr, 1u);
            __syncthreads();
            if (s_old == tgt6 - 1u) {          // last of 6 tiles: do the gate
                if (!layer2) {
                    gate_chunk(g_gi, g_gh, h1p, h1c_, by, nx & 7);
                    __threadfence(); __syncthreads();
                    if (threadIdx.x == 0) atomicAdd(&g_h1c[by], 1u);
                } else {
                    const float* hp2 = (t == 0) ? h1c_ : h2p;
                    gate_chunk(g_gi, g_gh, hp2, h2c_, by, nx & 7);
                    __threadfence(); __syncthreads();
                    if (threadIdx.x == 0) atomicAdd(&g_h2c[by], 1u);
                }
            }
        } else {
            unsigned w = u - 1536u;            // 64 wout units of 32 rows
            int m0 = (int)w * 32;
            if (threadIdx.x == 0) {
                while (*(volatile unsigned*)&g_h2c[m0 >> 7] < tgt8) {}
                __threadfence();
            }
            __syncthreads();
            wout_unit(smem, h2c_, Wo, bo, dout, g_inp, m0, t);
        }
    }
}

// ============ prologue kernels =============================================
#define SBM 128
#define SBN 64
#define SBK 16

template<int ACT>
__global__ void __launch_bounds__(256, 4) gemm_kernel(
    const float* __restrict__ A, int lda,
    const float* __restrict__ W, int ldw,
    const float* __restrict__ bias,
    float* __restrict__ C,
    int N, int K)
{
    __shared__ float As[SBK][SBM + 4];
    __shared__ float Bs[SBK][SBN + 4];

    const int tid = threadIdx.x;
    const int tx  = tid & 15;
    const int ty  = tid >> 4;
    const int m0  = blockIdx.y * SBM;
    const int n0  = blockIdx.x * SBN;

    float acc[8][4];
    #pragma unroll
    for (int i = 0; i < 8; i++)
        #pragma unroll
        for (int j = 0; j < 4; j++) acc[i][j] = 0.f;

    for (int kt = 0; kt < K; kt += SBK) {
        #pragma unroll
        for (int l = 0; l < 2; l++) {
            int idx4 = tid + l * 256;
            int r = idx4 >> 2, c4 = idx4 & 3;
            float4 v = *reinterpret_cast<const float4*>(
                A + (size_t)(m0 + r) * lda + kt + c4 * 4);
            As[c4*4+0][r] = v.x; As[c4*4+1][r] = v.y;
            As[c4*4+2][r] = v.z; As[c4*4+3][r] = v.w;
        }
        {
            int r = tid >> 2, c4 = tid & 3;
            float4 v = *reinterpret_cast<const float4*>(
                W + (size_t)(n0 + r) * ldw + kt + c4 * 4);
            Bs[c4*4+0][r] = v.x; Bs[c4*4+1][r] = v.y;
            Bs[c4*4+2][r] = v.z; Bs[c4*4+3][r] = v.w;
        }
        __syncthreads();

        #pragma unroll
        for (int k = 0; k < SBK; k++) {
            float4 a0 = *reinterpret_cast<const float4*>(&As[k][ty * 8]);
            float4 a1 = *reinterpret_cast<const float4*>(&As[k][ty * 8 + 4]);
            float4 b0 = *reinterpret_cast<const float4*>(&Bs[k][tx * 4]);
            float av[8] = {a0.x, a0.y, a0.z, a0.w, a1.x, a1.y, a1.z, a1.w};
            float bv[4] = {b0.x, b0.y, b0.z, b0.w};
            #pragma unroll
            for (int i = 0; i < 8; i++)
                #pragma unroll
                for (int j = 0; j < 4; j++)
                    acc[i][j] = fmaf(av[i], bv[j], acc[i][j]);
        }
        __syncthreads();
    }

    float4 b4 = make_float4(0.f, 0.f, 0.f, 0.f);
    if (bias) b4 = *reinterpret_cast<const float4*>(bias + n0 + tx * 4);

    #pragma unroll
    for (int i = 0; i < 8; i++) {
        int m = m0 + ty * 8 + i;
        size_t off = (size_t)m * N + n0 + tx * 4;
        float4 v = make_float4(__fadd_rn(acc[i][0], b4.x),
                               __fadd_rn(acc[i][1], b4.y),
                               __fadd_rn(acc[i][2], b4.z),
                               __fadd_rn(acc[i][3], b4.w));
        if (ACT == 1) {
            v.x = tanhf(v.x); v.y = tanhf(v.y);
            v.z = tanhf(v.z); v.w = tanhf(v.w);
        }
        *reinterpret_cast<float4*>(C + off) = v;
    }
}

__global__ void init_inp_kernel(const float* __restrict__ z,
                                float* __restrict__ inp)
{
    int i = blockIdx.x * blockDim.x + threadIdx.x;
    int b = i >> 9;
    int j = i & (KIN - 1);
    float v;
    if (j < D) v = (j == D - 1) ? 1.f : 0.f;
    else       v = z[(size_t)b * L + (j - D)];
    inp[i] = v;
}

// ---------------- launch ---------------------------------------------------
extern "C" void kernel_launch(void* const* d_in, const int* in_sizes, int n_in,
                              void* d_out, int out_size)
{
    (void)in_sizes; (void)n_in; (void)out_size;
    const float* z      = (const float*)d_in[0];
    const float* W_init = (const float*)d_in[1];
    const float* b_init = (const float*)d_in[2];
    const float* W_ih1  = (const float*)d_in[3];   // [3072, 512]
    const float* W_hh1  = (const float*)d_in[4];   // [3072, 1024]
    const float* b_ih1  = (const float*)d_in[5];
    const float* b_hh1  = (const float*)d_in[6];
    const float* W_ih2  = (const float*)d_in[7];
    const float* W_hh2  = (const float*)d_in[8];
    const float* b_ih2  = (const float*)d_in[9];
    const float* b_hh2  = (const float*)d_in[10];
    const float* W_out  = (const float*)d_in[11];  // [256, 1024]
    const float* b_out  = (const float*)d_in[12];
    float* out = (float*)d_out;

    float *inp, *h1;
    cudaGetSymbolAddress((void**)&inp, g_inp);
    cudaGetSymbolAddress((void**)&h1,  g_h1);
    float* h1_prev0 = h1 + (size_t)B * H;   // parity-1 buffer (prev of step 0)

    const dim3 blk(256);
    const dim3 grid_h(H / SBN, B / SBM);

    // 1: dummy (ncu -s 5 lands on step_kernel t=0)
    dummy_kernel<<<1, 32>>>();
    // 2: inp = [one_hot | z]
    init_inp_kernel<<<(B * KIN) / 256, blk>>>(z, inp);
    // 3: h1_prev = tanh(z @ W_init^T + b_init)
    gemm_kernel<1><<<grid_h, blk>>>(z, L, W_init, L, b_init, h1_prev0, H, L);
    // 4: zero counters + queues (replay-safe)
    zero_kernel<<<2, 256>>>();

    // 5..68: one persistent dataflow launch per step
    for (int t = 0; t < NSTEP; t++) {
        step_kernel<<<NBLK, TPB>>>(W_ih1, b_ih1, W_hh1, b_hh1,
                                   W_ih2, b_ih2, W_hh2, b_hh2,
                                   W_out, b_out, out, t);
    }
}

// round 13
// speedup vs baseline: 1.0275x; 1.0275x over previous
#include <cuda_runtime.h>
#include <math.h>

// R12: R11 dataflow kernel, with the wout epilogue de-concentrated:
// 256 wout units of 32x64 (R10 tile shape, bit-identical chain) + inline
// 32-row softmax by the 4th-tile finisher. Numerics invariant throughout.

// Problem constants
#define B     2048
#define L     256
#define H     1024
#define D     256
#define NSTEP 64
#define G3H   (3*H)   // 3072
#define KIN   (D + L) // 512

#define NBLK  296     // 2 CTAs/SM x 148 SMs
#define TPB   256
#define UNITS 1792    // 4*384 GEMM tiles + 256 wout units

// ---------------- scratch (device globals: allocation-free) ----------------
__device__ float g_inp[(size_t)B * KIN];
__device__ float g_gi [(size_t)B * G3H];
__device__ float g_gh [(size_t)B * G3H];
__device__ float g_h1 [2 * (size_t)B * H];   // parity double-buffer
__device__ float g_h2 [2 * (size_t)B * H];
__device__ float g_tmp[(size_t)B * D];       // logits

// dependency counters (monotonic across steps within one kernel_launch)
__device__ unsigned g_c1 [16 * 8];   // gate1 chunk counters (by, jx)
__device__ unsigned g_c2 [16 * 8];   // gate2 chunk counters
__device__ unsigned g_h1c[16];       // h1 slab ready (per by)
__device__ unsigned g_h2c[16];       // h2 slab ready
__device__ unsigned g_wc [64];       // wout m-block counters
__device__ unsigned g_q  [NSTEP];    // per-step work queues

struct SmemGemm { float As[2][16][132]; float Bs[2][16][132]; };  // 33792 B
struct SmemWout { float As[16][36];     float Bs[16][68];     };
#define SMEM_BYTES 33792

__global__ void zero_kernel()
{
    int i = blockIdx.x * blockDim.x + threadIdx.x;
    if      (i < 128)          g_c1 [i]       = 0;
    else if (i < 256)          g_c2 [i - 128] = 0;
    else if (i < 272)          g_h1c[i - 256] = 0;
    else if (i < 288)          g_h2c[i - 272] = 0;
    else if (i < 352)          g_wc [i - 288] = 0;
    else if (i < 352 + NSTEP)  g_q  [i - 352] = 0;
}

// ============ 128x128 GEMM tile (byte-identical serial-k chain) ============
__device__ __noinline__ void gemm_tile(char* smemraw,
    const float* __restrict__ A, int lda,
    const float* __restrict__ W, int ldw,
    const float* __restrict__ bias,
    float* __restrict__ C, int K, int m0, int n0)
{
    SmemGemm& sh = *reinterpret_cast<SmemGemm*>(smemraw);
    const int tid = threadIdx.x;
    const int tx  = tid & 15;
    const int ty  = tid >> 4;
    const int r0  = tid >> 2;
    const int c4  = tid & 3;

    const float* Ap = A + (size_t)(m0 + r0) * lda + c4 * 4;
    const float* Wp = W + (size_t)(n0 + r0) * ldw + c4 * 4;

    float acc[8][8];
    #pragma unroll
    for (int i = 0; i < 8; i++)
        #pragma unroll
        for (int j = 0; j < 8; j++) acc[i][j] = 0.f;

    float4 pa[2], pb[2];
    int cur = 0;

    auto fetchA = [&](int kt) {
        pa[0] = *reinterpret_cast<const float4*>(Ap + kt);
        pa[1] = *reinterpret_cast<const float4*>(Ap + (size_t)64 * lda + kt);
    };
    auto fetchB = [&](int kt) {
        pb[0] = *reinterpret_cast<const float4*>(Wp + kt);
        pb[1] = *reinterpret_cast<const float4*>(Wp + (size_t)64 * ldw + kt);
    };
    auto storeA = [&](int buf) {
        sh.As[buf][c4*4+0][r0] = pa[0].x; sh.As[buf][c4*4+1][r0] = pa[0].y;
        sh.As[buf][c4*4+2][r0] = pa[0].z; sh.As[buf][c4*4+3][r0] = pa[0].w;
        sh.As[buf][c4*4+0][r0+64] = pa[1].x; sh.As[buf][c4*4+1][r0+64] = pa[1].y;
        sh.As[buf][c4*4+2][r0+64] = pa[1].z; sh.As[buf][c4*4+3][r0+64] = pa[1].w;
    };
    auto storeB = [&](int buf) {
        sh.Bs[buf][c4*4+0][r0] = pb[0].x; sh.Bs[buf][c4*4+1][r0] = pb[0].y;
        sh.Bs[buf][c4*4+2][r0] = pb[0].z; sh.Bs[buf][c4*4+3][r0] = pb[0].w;
        sh.Bs[buf][c4*4+0][r0+64] = pb[1].x; sh.Bs[buf][c4*4+1][r0+64] = pb[1].y;
        sh.Bs[buf][c4*4+2][r0+64] = pb[1].z; sh.Bs[buf][c4*4+3][r0+64] = pb[1].w;
    };

    float a_fr[2][8], b_fr[2][8];
    auto load_frag = [&](int k, int s) {
        float4 a0 = *reinterpret_cast<const float4*>(&sh.As[cur][k][ty * 4]);
        float4 a1 = *reinterpret_cast<const float4*>(&sh.As[cur][k][64 + ty * 4]);
        float4 b0 = *reinterpret_cast<const float4*>(&sh.Bs[cur][k][tx * 4]);
        float4 b1 = *reinterpret_cast<const float4*>(&sh.Bs[cur][k][64 + tx * 4]);
        a_fr[s][0]=a0.x; a_fr[s][1]=a0.y; a_fr[s][2]=a0.z; a_fr[s][3]=a0.w;
        a_fr[s][4]=a1.x; a_fr[s][5]=a1.y; a_fr[s][6]=a1.z; a_fr[s][7]=a1.w;
        b_fr[s][0]=b0.x; b_fr[s][1]=b0.y; b_fr[s][2]=b0.z; b_fr[s][3]=b0.w;
        b_fr[s][4]=b1.x; b_fr[s][5]=b1.y; b_fr[s][6]=b1.z; b_fr[s][7]=b1.w;
    };

    const int ntiles = K / 16;
    fetchA(0); fetchB(0);
    storeA(0); storeB(0);
    __syncthreads();

    for (int t = 0; t < ntiles; t++) {
        const bool hn = (t + 1 < ntiles);
        if (hn) { fetchA((t + 1) * 16); fetchB((t + 1) * 16); }

        load_frag(0, 0);
        #pragma unroll
        for (int k = 0; k < 16; k++) {
            const int s = k & 1;
            if (k + 1 < 16) load_frag(k + 1, s ^ 1);
            if (k == 9  && hn) storeA(cur ^ 1);
            if (k == 13 && hn) storeB(cur ^ 1);
            #pragma unroll
            for (int i = 0; i < 8; i++)
                #pragma unroll
                for (int j = 0; j < 8; j++)
                    acc[i][j] = fmaf(a_fr[s][i], b_fr[s][j], acc[i][j]);
        }
        __syncthreads();
        if (hn) cur ^= 1;
    }

    float4 bb0 = *reinterpret_cast<const float4*>(bias + n0 + tx * 4);
    float4 bb1 = *reinterpret_cast<const float4*>(bias + n0 + 64 + tx * 4);

    #pragma unroll
    for (int i = 0; i < 8; i++) {
        int m = m0 + ((i < 4) ? (ty * 4 + i) : (64 + ty * 4 + (i - 4)));
        size_t off = (size_t)m * G3H + n0;
        float4 v0 = make_float4(__fadd_rn(acc[i][0], bb0.x),
                                __fadd_rn(acc[i][1], bb0.y),
                                __fadd_rn(acc[i][2], bb0.z),
                                __fadd_rn(acc[i][3], bb0.w));
        float4 v1 = make_float4(__fadd_rn(acc[i][4], bb1.x),
                                __fadd_rn(acc[i][5], bb1.y),
                                __fadd_rn(acc[i][6], bb1.z),
                                __fadd_rn(acc[i][7], bb1.w));
        *reinterpret_cast<float4*>(C + off + tx * 4)      = v0;
        *reinterpret_cast<float4*>(C + off + 64 + tx * 4) = v1;
    }
}

// ============ 128x128 GRU gate chunk (same formulas) =======================
__device__ __noinline__ void gate_chunk(
    const float* __restrict__ gi, const float* __restrict__ gh,
    const float* __restrict__ hprev, float* __restrict__ hout,
    int by, int jx)
{
    const int tid = threadIdx.x;
    const int cc  = (tid & 31) * 4;
    const int r8  = tid >> 5;
    const int b0  = by * 128;
    const int jb  = jx * 128;

    for (int i = 0; i < 16; i++) {
        int row = b0 + r8 + i * 8;
        int j   = jb + cc;
        size_t gb = (size_t)row * G3H + j;
        size_t hb = (size_t)row * H + j;
        float4 ir4 = *reinterpret_cast<const float4*>(gi + gb);
        float4 iz4 = *reinterpret_cast<const float4*>(gi + gb + H);
        float4 in4 = *reinterpret_cast<const float4*>(gi + gb + 2 * H);
        float4 hr4 = *reinterpret_cast<const float4*>(gh + gb);
        float4 hz4 = *reinterpret_cast<const float4*>(gh + gb + H);
        float4 hn4 = *reinterpret_cast<const float4*>(gh + gb + 2 * H);
        float4 hp4 = *reinterpret_cast<const float4*>(hprev + hb);

        float hv[4];
        const float ir[4] = {ir4.x, ir4.y, ir4.z, ir4.w};
        const float iz[4] = {iz4.x, iz4.y, iz4.z, iz4.w};
        const float in_[4] = {in4.x, in4.y, in4.z, in4.w};
        const float hr[4] = {hr4.x, hr4.y, hr4.z, hr4.w};
        const float hz[4] = {hz4.x, hz4.y, hz4.z, hz4.w};
        const float hn[4] = {hn4.x, hn4.y, hn4.z, hn4.w};
        const float hp[4] = {hp4.x, hp4.y, hp4.z, hp4.w};
        #pragma unroll
        for (int e = 0; e < 4; e++) {
            float sr = __fadd_rn(ir[e], hr[e]);
            float sz = __fadd_rn(iz[e], hz[e]);
            float r  = __fdiv_rn(1.f, __fadd_rn(1.f, expf(-sr)));
            float zg = __fdiv_rn(1.f, __fadd_rn(1.f, expf(-sz)));
            float n  = tanhf(__fadd_rn(in_[e], __fmul_rn(r, hn[e])));
            hv[e] = __fadd_rn(__fmul_rn(__fsub_rn(1.f, zg), n),
                              __fmul_rn(zg, hp[e]));
        }
        *reinterpret_cast<float4*>(hout + hb) =
            make_float4(hv[0], hv[1], hv[2], hv[3]);
    }
}

// ============ W_out tile 32x64 (R10 body, bit-identical) ===================
__device__ __noinline__ void wout_tile(char* smemraw,
    const float* __restrict__ A, const float* __restrict__ Wo,
    const float* __restrict__ bo, float* __restrict__ tmp,
    int m0, int n0)
{
    SmemWout& sh = *reinterpret_cast<SmemWout*>(smemraw);
    const int tid = threadIdx.x;
    const int tx  = tid & 15;
    const int ty  = tid >> 4;

    float acc[2][4];
    #pragma unroll
    for (int i = 0; i < 2; i++)
        #pragma unroll
        for (int j = 0; j < 4; j++) acc[i][j] = 0.f;

    for (int kt = 0; kt < H; kt += 16) {
        if (tid < 128) {
            int r = tid >> 2, c4 = tid & 3;
            float4 v = *reinterpret_cast<const float4*>(
                A + (size_t)(m0 + r) * H + kt + c4 * 4);
            sh.As[c4*4+0][r] = v.x; sh.As[c4*4+1][r] = v.y;
            sh.As[c4*4+2][r] = v.z; sh.As[c4*4+3][r] = v.w;
        }
        {
            int r = tid >> 2, c4 = tid & 3;
            float4 v = *reinterpret_cast<const float4*>(
                Wo + (size_t)(n0 + r) * H + kt + c4 * 4);
            sh.Bs[c4*4+0][r] = v.x; sh.Bs[c4*4+1][r] = v.y;
            sh.Bs[c4*4+2][r] = v.z; sh.Bs[c4*4+3][r] = v.w;
        }
        __syncthreads();

        #pragma unroll
        for (int k = 0; k < 16; k++) {
            float a0 = sh.As[k][ty * 2];
            float a1 = sh.As[k][ty * 2 + 1];
            float4 b = *reinterpret_cast<const float4*>(&sh.Bs[k][tx * 4]);
            float bv[4] = {b.x, b.y, b.z, b.w};
            #pragma unroll
            for (int j = 0; j < 4; j++) {
                acc[0][j] = fmaf(a0, bv[j], acc[0][j]);
                acc[1][j] = fmaf(a1, bv[j], acc[1][j]);
            }
        }
        __syncthreads();
    }

    float4 b4 = *reinterpret_cast<const float4*>(bo + n0 + tx * 4);
    #pragma unroll
    for (int i = 0; i < 2; i++) {
        int m = m0 + ty * 2 + i;
        size_t off = (size_t)m * D + n0 + tx * 4;
        float4 v = make_float4(__fadd_rn(acc[i][0], b4.x),
                               __fadd_rn(acc[i][1], b4.y),
                               __fadd_rn(acc[i][2], b4.z),
                               __fadd_rn(acc[i][3], b4.w));
        *reinterpret_cast<float4*>(tmp + off) = v;
    }
}

// ============ 32-row softmax (reference order, same as R10) ================
__device__ __noinline__ void softmax_rows(
    const float* __restrict__ tmp, float* __restrict__ inp,
    float* __restrict__ dout, int m0, int t)
{
    const int tid = threadIdx.x;
    for (int i = 0; i < 16; i++) {
        int p = i * 256 + tid;            // 4096 pairs (32 rows x 128)
        int r = p >> 7;
        int f = p & 127;
        int b_ = m0 + r;
        float a = tmp[(size_t)b_ * D + f];
        float c = tmp[(size_t)b_ * D + 128 + f];
        float m  = fmaxf(a, c);
        float sa = __fsub_rn(a, m);
        float sc = __fsub_rn(c, m);
        float lse = logf(__fadd_rn(expf(sa), expf(sc)));
        float la = __fsub_rn(sa, lse);
        float lc = __fsub_rn(sc, lse);
        size_t ob = (size_t)b_ * NSTEP * D + (size_t)t * D;
        dout[ob + f]       = la;
        dout[ob + 128 + f] = lc;
        int idx = (la >= lc) ? 0 : 1;
        inp[(size_t)b_ * KIN + 2 * f]     = (idx == 0) ? 1.f : 0.f;
        inp[(size_t)b_ * KIN + 2 * f + 1] = (idx == 1) ? 1.f : 0.f;
    }
}

// ============ persistent per-step kernel ===================================
__global__ void __launch_bounds__(TPB, 2) step_kernel(
    const float* __restrict__ Wih1, const float* __restrict__ bih1,
    const float* __restrict__ Whh1, const float* __restrict__ bhh1,
    const float* __restrict__ Wih2, const float* __restrict__ bih2,
    const float* __restrict__ Whh2, const float* __restrict__ bhh2,
    const float* __restrict__ Wo,   const float* __restrict__ bo,
    float* __restrict__ dout, int t)
{
    __shared__ __align__(16) char smem[SMEM_BYTES];
    __shared__ unsigned s_u, s_old;

    const int cur = t & 1, prv = cur ^ 1;
    float* h1c_ = g_h1 + (size_t)cur * B * H;
    float* h1p  = g_h1 + (size_t)prv * B * H;
    float* h2c_ = g_h2 + (size_t)cur * B * H;
    float* h2p  = g_h2 + (size_t)prv * B * H;
    const unsigned tgt6 = 6u * (t + 1);
    const unsigned tgt8 = 8u * (t + 1);
    const unsigned tgt4 = 4u * (t + 1);

    for (;;) {
        if (threadIdx.x == 0) s_u = atomicAdd(&g_q[t], 1u);
        __syncthreads();
        unsigned u = s_u;
        if (u >= UNITS) break;

        if (u < 1536u) {
            unsigned seg = u / 384u, v = u % 384u;
            int nx = (int)(v % 24u), by = (int)(v / 24u);
            const bool layer2 = (seg >= 2);

            if (layer2) {
                if (threadIdx.x == 0) {
                    while (*(volatile unsigned*)&g_h1c[by] < tgt8) {}
                    __threadfence();
                }
                __syncthreads();
            }
            const float *A, *W, *bias; float* Cd; int lda, ldw, K;
            if (seg == 0)      { A=h1p;   lda=H;   W=Whh1; ldw=H;   bias=bhh1; Cd=g_gh; K=H;   }
            else if (seg == 1) { A=g_inp; lda=KIN; W=Wih1; ldw=KIN; bias=bih1; Cd=g_gi; K=KIN; }
            else if (seg == 2) { A=h1c_;  lda=H;   W=Wih2; ldw=H;   bias=bih2; Cd=g_gi; K=H;   }
            else               { A=(t==0 ? h1c_ : h2p);
                                 lda=H;   W=Whh2; ldw=H;   bias=bhh2; Cd=g_gh; K=H;   }

            gemm_tile(smem, A, lda, W, ldw, bias, Cd, K, by * 128, nx * 128);

            __threadfence();
            __syncthreads();
            unsigned* ctr = layer2 ? &g_c2[by * 8 + (nx & 7)]
                                   : &g_c1[by * 8 + (nx & 7)];
            if (threadIdx.x == 0) s_old = atomicAdd(ctr, 1u);
            __syncthreads();
            if (s_old == tgt6 - 1u) {
                if (!layer2) {
                    gate_chunk(g_gi, g_gh, h1p, h1c_, by, nx & 7);
                    __threadfence(); __syncthreads();
                    if (threadIdx.x == 0) atomicAdd(&g_h1c[by], 1u);
                } else {
                    const float* hp2 = (t == 0) ? h1c_ : h2p;
                    gate_chunk(g_gi, g_gh, hp2, h2c_, by, nx & 7);
                    __threadfence(); __syncthreads();
                    if (threadIdx.x == 0) atomicAdd(&g_h2c[by], 1u);
                }
            }
        } else {
            unsigned w = u - 1536u;            // 256 wout tiles of 32x64
            int mb = (int)(w >> 2);            // m-block 0..63 (32 rows)
            int m0 = mb * 32;
            int n0 = (int)(w & 3u) * 64;
            if (threadIdx.x == 0) {
                while (*(volatile unsigned*)&g_h2c[m0 >> 7] < tgt8) {}
                __threadfence();
            }
            __syncthreads();
            wout_tile(smem, h2c_, Wo, bo, g_tmp, m0, n0);
            __threadfence();
            __syncthreads();
            if (threadIdx.x == 0) s_old = atomicAdd(&g_wc[mb], 1u);
            __syncthreads();
            if (s_old == tgt4 - 1u)
                softmax_rows(g_tmp, g_inp, dout, m0, t);
        }
    }
}

// ============ prologue kernels =============================================
#define SBM 128
#define SBN 64
#define SBK 16

template<int ACT>
__global__ void __launch_bounds__(256, 4) gemm_kernel(
    const float* __restrict__ A, int lda,
    const float* __restrict__ W, int ldw,
    const float* __restrict__ bias,
    float* __restrict__ C,
    int N, int K)
{
    __shared__ float As[SBK][SBM + 4];
    __shared__ float Bs[SBK][SBN + 4];

    const int tid = threadIdx.x;
    const int tx  = tid & 15;
    const int ty  = tid >> 4;
    const int m0  = blockIdx.y * SBM;
    const int n0  = blockIdx.x * SBN;

    float acc[8][4];
    #pragma unroll
    for (int i = 0; i < 8; i++)
        #pragma unroll
        for (int j = 0; j < 4; j++) acc[i][j] = 0.f;

    for (int kt = 0; kt < K; kt += SBK) {
        #pragma unroll
        for (int l = 0; l < 2; l++) {
            int idx4 = tid + l * 256;
            int r = idx4 >> 2, c4 = idx4 & 3;
            float4 v = *reinterpret_cast<const float4*>(
                A + (size_t)(m0 + r) * lda + kt + c4 * 4);
            As[c4*4+0][r] = v.x; As[c4*4+1][r] = v.y;
            As[c4*4+2][r] = v.z; As[c4*4+3][r] = v.w;
        }
        {
            int r = tid >> 2, c4 = tid & 3;
            float4 v = *reinterpret_cast<const float4*>(
                W + (size_t)(n0 + r) * ldw + kt + c4 * 4);
            Bs[c4*4+0][r] = v.x; Bs[c4*4+1][r] = v.y;
            Bs[c4*4+2][r] = v.z; Bs[c4*4+3][r] = v.w;
        }
        __syncthreads();

        #pragma unroll
        for (int k = 0; k < SBK; k++) {
            float4 a0 = *reinterpret_cast<const float4*>(&As[k][ty * 8]);
            float4 a1 = *reinterpret_cast<const float4*>(&As[k][ty * 8 + 4]);
            float4 b0 = *reinterpret_cast<const float4*>(&Bs[k][tx * 4]);
            float av[8] = {a0.x, a0.y, a0.z, a0.w, a1.x, a1.y, a1.z, a1.w};
            float bv[4] = {b0.x, b0.y, b0.z, b0.w};
            #pragma unroll
            for (int i = 0; i < 8; i++)
                #pragma unroll
                for (int j = 0; j < 4; j++)
                    acc[i][j] = fmaf(av[i], bv[j], acc[i][j]);
        }
        __syncthreads();
    }

    float4 b4 = make_float4(0.f, 0.f, 0.f, 0.f);
    if (bias) b4 = *reinterpret_cast<const float4*>(bias + n0 + tx * 4);

    #pragma unroll
    for (int i = 0; i < 8; i++) {
        int m = m0 + ty * 8 + i;
        size_t off = (size_t)m * N + n0 + tx * 4;
        float4 v = make_float4(__fadd_rn(acc[i][0], b4.x),
                               __fadd_rn(acc[i][1], b4.y),
                               __fadd_rn(acc[i][2], b4.z),
                               __fadd_rn(acc[i][3], b4.w));
        if (ACT == 1) {
            v.x = tanhf(v.x); v.y = tanhf(v.y);
            v.z = tanhf(v.z); v.w = tanhf(v.w);
        }
        *reinterpret_cast<float4*>(C + off) = v;
    }
}

__global__ void init_inp_kernel(const float* __restrict__ z,
                                float* __restrict__ inp)
{
    int i = blockIdx.x * blockDim.x + threadIdx.x;
    int b = i >> 9;
    int j = i & (KIN - 1);
    float v;
    if (j < D) v = (j == D - 1) ? 1.f : 0.f;
    else       v = z[(size_t)b * L + (j - D)];
    inp[i] = v;
}

// ---------------- launch ---------------------------------------------------
extern "C" void kernel_launch(void* const* d_in, const int* in_sizes, int n_in,
                              void* d_out, int out_size)
{
    (void)in_sizes; (void)n_in; (void)out_size;
    const float* z      = (const float*)d_in[0];
    const float* W_init = (const float*)d_in[1];
    const float* b_init = (const float*)d_in[2];
    const float* W_ih1  = (const float*)d_in[3];   // [3072, 512]
    const float* W_hh1  = (const float*)d_in[4];   // [3072, 1024]
    const float* b_ih1  = (const float*)d_in[5];
    const float* b_hh1  = (const float*)d_in[6];
    const float* W_ih2  = (const float*)d_in[7];
    const float* W_hh2  = (const float*)d_in[8];
    const float* b_ih2  = (const float*)d_in[9];
    const float* b_hh2  = (const float*)d_in[10];
    const float* W_out  = (const float*)d_in[11];  // [256, 1024]
    const float* b_out  = (const float*)d_in[12];
    float* out = (float*)d_out;

    float *inp, *h1;
    cudaGetSymbolAddress((void**)&inp, g_inp);
    cudaGetSymbolAddress((void**)&h1,  g_h1);
    float* h1_prev0 = h1 + (size_t)B * H;   // parity-1 buffer (prev of step 0)

    const dim3 blk(256);
    const dim3 grid_h(H / SBN, B / SBM);

    // launches: init(1), gemm_h(2), zero(3), step0(4 <- profiled), ...
    init_inp_kernel<<<(B * KIN) / 256, blk>>>(z, inp);
    gemm_kernel<1><<<grid_h, blk>>>(z, L, W_init, L, b_init, h1_prev0, H, L);
    zero_kernel<<<2, 256>>>();

    for (int t = 0; t < NSTEP; t++) {
        step_kernel<<<NBLK, TPB>>>(W_ih1, b_ih1, W_hh1, b_hh1,
                                   W_ih2, b_ih2, W_hh2, b_hh2,
                                   W_out, b_out, out, t);
    }
}

// round 14
// speedup vs baseline: 1.0878x; 1.0587x over previous
#include <cuda_runtime.h>
#include <math.h>

// R13: R10 kernels, restructured as a two-stream CUDA-graph DAG.
// Critical chain (stream M): gi1 -> gate1 -> gi2 -> gate2 -> wout -> softmax.
// Off-chain (stream P):      gh1(t+1) after gate1(t), gh2(t+1) after gate2(t).
// Numerics invariant: serial ascending-k fp32 FMA chain per output, post-sum
// bias, de-fused gates, reference-ordered log-softmax.

#define B     2048
#define L     256
#define H     1024
#define D     256
#define NSTEP 64
#define G3H   (3*H)   // 3072
#define KIN   (D + L) // 512

// ---------------- scratch (device globals: allocation-free) ----------------
__device__ float g_inp [(size_t)B * KIN];
__device__ float g_gi1 [(size_t)B * G3H];
__device__ float g_gh1 [(size_t)B * G3H];
__device__ float g_gi2 [(size_t)B * G3H];
__device__ float g_gh2 [(size_t)B * G3H];
__device__ float g_h1  [(size_t)B * H];
__device__ float g_h2  [(size_t)B * H];
__device__ float g_tmp [(size_t)B * D];

// ============ 128x128 GEMM: C[B,G3H] = A @ W^T + bias (R10 body) ===========
#define BM 128
#define BN 128
#define NT 256

__global__ void __launch_bounds__(NT, 2) gemm3h_kernel(
    const float* __restrict__ A, int lda,
    const float* __restrict__ W, int ldw,
    const float* __restrict__ bias,
    float* __restrict__ C, int K)
{
    __shared__ float As[2][16][BM + 4];
    __shared__ float Bs[2][16][BN + 4];

    const int tid = threadIdx.x;
    const int tx  = tid & 15;
    const int ty  = tid >> 4;
    const int m0  = blockIdx.y * BM;
    const int n0  = blockIdx.x * BN;
    const int r0  = tid >> 2;
    const int c4  = tid & 3;

    const float* Ap = A + (size_t)(m0 + r0) * lda + c4 * 4;
    const float* Wp = W + (size_t)(n0 + r0) * ldw + c4 * 4;

    float acc[8][8];
    #pragma unroll
    for (int i = 0; i < 8; i++)
        #pragma unroll
        for (int j = 0; j < 8; j++) acc[i][j] = 0.f;

    float4 pa[2], pb[2];
    int cur = 0;

    auto fetchA = [&](int kt) {
        pa[0] = *reinterpret_cast<const float4*>(Ap + kt);
        pa[1] = *reinterpret_cast<const float4*>(Ap + (size_t)64 * lda + kt);
    };
    auto fetchB = [&](int kt) {
        pb[0] = *reinterpret_cast<const float4*>(Wp + kt);
        pb[1] = *reinterpret_cast<const float4*>(Wp + (size_t)64 * ldw + kt);
    };
    auto storeA = [&](int buf) {
        As[buf][c4*4+0][r0] = pa[0].x; As[buf][c4*4+1][r0] = pa[0].y;
        As[buf][c4*4+2][r0] = pa[0].z; As[buf][c4*4+3][r0] = pa[0].w;
        As[buf][c4*4+0][r0+64] = pa[1].x; As[buf][c4*4+1][r0+64] = pa[1].y;
        As[buf][c4*4+2][r0+64] = pa[1].z; As[buf][c4*4+3][r0+64] = pa[1].w;
    };
    auto storeB = [&](int buf) {
        Bs[buf][c4*4+0][r0] = pb[0].x; Bs[buf][c4*4+1][r0] = pb[0].y;
        Bs[buf][c4*4+2][r0] = pb[0].z; Bs[buf][c4*4+3][r0] = pb[0].w;
        Bs[buf][c4*4+0][r0+64] = pb[1].x; Bs[buf][c4*4+1][r0+64] = pb[1].y;
        Bs[buf][c4*4+2][r0+64] = pb[1].z; Bs[buf][c4*4+3][r0+64] = pb[1].w;
    };

    float a_fr[2][8], b_fr[2][8];
    auto load_frag = [&](int k, int s) {
        float4 a0 = *reinterpret_cast<const float4*>(&As[cur][k][ty * 4]);
        float4 a1 = *reinterpret_cast<const float4*>(&As[cur][k][64 + ty * 4]);
        float4 b0 = *reinterpret_cast<const float4*>(&Bs[cur][k][tx * 4]);
        float4 b1 = *reinterpret_cast<const float4*>(&Bs[cur][k][64 + tx * 4]);
        a_fr[s][0]=a0.x; a_fr[s][1]=a0.y; a_fr[s][2]=a0.z; a_fr[s][3]=a0.w;
        a_fr[s][4]=a1.x; a_fr[s][5]=a1.y; a_fr[s][6]=a1.z; a_fr[s][7]=a1.w;
        b_fr[s][0]=b0.x; b_fr[s][1]=b0.y; b_fr[s][2]=b0.z; b_fr[s][3]=b0.w;
        b_fr[s][4]=b1.x; b_fr[s][5]=b1.y; b_fr[s][6]=b1.z; b_fr[s][7]=b1.w;
    };

    const int ntiles = K / 16;
    fetchA(0); fetchB(0);
    storeA(0); storeB(0);
    __syncthreads();

    for (int t = 0; t < ntiles; t++) {
        const bool hn = (t + 1 < ntiles);
        if (hn) { fetchA((t + 1) * 16); fetchB((t + 1) * 16); }

        load_frag(0, 0);
        #pragma unroll
        for (int k = 0; k < 16; k++) {
            const int s = k & 1;
            if (k + 1 < 16) load_frag(k + 1, s ^ 1);
            if (k == 9  && hn) storeA(cur ^ 1);
            if (k == 13 && hn) storeB(cur ^ 1);
            #pragma unroll
            for (int i = 0; i < 8; i++)
                #pragma unroll
                for (int j = 0; j < 8; j++)
                    acc[i][j] = fmaf(a_fr[s][i], b_fr[s][j], acc[i][j]);
        }
        __syncthreads();
        if (hn) cur ^= 1;
    }

    float4 bb0 = *reinterpret_cast<const float4*>(bias + n0 + tx * 4);
    float4 bb1 = *reinterpret_cast<const float4*>(bias + n0 + 64 + tx * 4);

    #pragma unroll
    for (int i = 0; i < 8; i++) {
        int m = m0 + ((i < 4) ? (ty * 4 + i) : (64 + ty * 4 + (i - 4)));
        size_t off = (size_t)m * G3H + n0;
        float4 v0 = make_float4(__fadd_rn(acc[i][0], bb0.x),
                                __fadd_rn(acc[i][1], bb0.y),
                                __fadd_rn(acc[i][2], bb0.z),
                                __fadd_rn(acc[i][3], bb0.w));
        float4 v1 = make_float4(__fadd_rn(acc[i][4], bb1.x),
                                __fadd_rn(acc[i][5], bb1.y),
                                __fadd_rn(acc[i][6], bb1.z),
                                __fadd_rn(acc[i][7], bb1.w));
        *reinterpret_cast<float4*>(C + off + tx * 4)      = v0;
        *reinterpret_cast<float4*>(C + off + 64 + tx * 4) = v1;
    }
}

// ============ small GEMM (prologue h1 init) ================================
#define SBM 128
#define SBN 64

template<int ACT>
__global__ void __launch_bounds__(256, 4) gemm_kernel(
    const float* __restrict__ A, int lda,
    const float* __restrict__ W, int ldw,
    const float* __restrict__ bias,
    float* __restrict__ C,
    int N, int K)
{
    __shared__ float As[16][SBM + 4];
    __shared__ float Bs[16][SBN + 4];

    const int tid = threadIdx.x;
    const int tx  = tid & 15;
    const int ty  = tid >> 4;
    const int m0  = blockIdx.y * SBM;
    const int n0  = blockIdx.x * SBN;

    float acc[8][4];
    #pragma unroll
    for (int i = 0; i < 8; i++)
        #pragma unroll
        for (int j = 0; j < 4; j++) acc[i][j] = 0.f;

    for (int kt = 0; kt < K; kt += 16) {
        #pragma unroll
        for (int l = 0; l < 2; l++) {
            int idx4 = tid + l * 256;
            int r = idx4 >> 2, c4 = idx4 & 3;
            float4 v = *reinterpret_cast<const float4*>(
                A + (size_t)(m0 + r) * lda + kt + c4 * 4);
            As[c4*4+0][r] = v.x; As[c4*4+1][r] = v.y;
            As[c4*4+2][r] = v.z; As[c4*4+3][r] = v.w;
        }
        {
            int r = tid >> 2, c4 = tid & 3;
            float4 v = *reinterpret_cast<const float4*>(
                W + (size_t)(n0 + r) * ldw + kt + c4 * 4);
            Bs[c4*4+0][r] = v.x; Bs[c4*4+1][r] = v.y;
            Bs[c4*4+2][r] = v.z; Bs[c4*4+3][r] = v.w;
        }
        __syncthreads();

        #pragma unroll
        for (int k = 0; k < 16; k++) {
            float4 a0 = *reinterpret_cast<const float4*>(&As[k][ty * 8]);
            float4 a1 = *reinterpret_cast<const float4*>(&As[k][ty * 8 + 4]);
            float4 b0 = *reinterpret_cast<const float4*>(&Bs[k][tx * 4]);
            float av[8] = {a0.x, a0.y, a0.z, a0.w, a1.x, a1.y, a1.z, a1.w};
            float bv[4] = {b0.x, b0.y, b0.z, b0.w};
            #pragma unroll
            for (int i = 0; i < 8; i++)
                #pragma unroll
                for (int j = 0; j < 4; j++)
                    acc[i][j] = fmaf(av[i], bv[j], acc[i][j]);
        }
        __syncthreads();
    }

    float4 b4 = make_float4(0.f, 0.f, 0.f, 0.f);
    if (bias) b4 = *reinterpret_cast<const float4*>(bias + n0 + tx * 4);

    #pragma unroll
    for (int i = 0; i < 8; i++) {
        int m = m0 + ty * 8 + i;
        size_t off = (size_t)m * N + n0 + tx * 4;
        float4 v = make_float4(__fadd_rn(acc[i][0], b4.x),
                               __fadd_rn(acc[i][1], b4.y),
                               __fadd_rn(acc[i][2], b4.z),
                               __fadd_rn(acc[i][3], b4.w));
        if (ACT == 1) {
            v.x = tanhf(v.x); v.y = tanhf(v.y);
            v.z = tanhf(v.z); v.w = tanhf(v.w);
        }
        *reinterpret_cast<float4*>(C + off) = v;
    }
}

// ============ W_out GEMM: 32x64 tiles (R10 body) ===========================
#define WBM 32
#define WBN 64

__global__ void __launch_bounds__(256, 4) gemm_wout_kernel(
    const float* __restrict__ A,
    const float* __restrict__ W,
    const float* __restrict__ bias,
    float* __restrict__ C)
{
    __shared__ float As[16][WBM + 4];
    __shared__ float Bs[16][WBN + 4];

    const int tid = threadIdx.x;
    const int tx  = tid & 15;
    const int ty  = tid >> 4;
    const int m0  = blockIdx.y * WBM;
    const int n0  = blockIdx.x * WBN;

    float acc[2][4];
    #pragma unroll
    for (int i = 0; i < 2; i++)
        #pragma unroll
        for (int j = 0; j < 4; j++) acc[i][j] = 0.f;

    for (int kt = 0; kt < H; kt += 16) {
        if (tid < 128) {
            int r = tid >> 2, c4 = tid & 3;
            float4 v = *reinterpret_cast<const float4*>(
                A + (size_t)(m0 + r) * H + kt + c4 * 4);
            As[c4*4+0][r] = v.x; As[c4*4+1][r] = v.y;
            As[c4*4+2][r] = v.z; As[c4*4+3][r] = v.w;
        }
        {
            int r = tid >> 2, c4 = tid & 3;
            float4 v = *reinterpret_cast<const float4*>(
                W + (size_t)(n0 + r) * H + kt + c4 * 4);
            Bs[c4*4+0][r] = v.x; Bs[c4*4+1][r] = v.y;
            Bs[c4*4+2][r] = v.z; Bs[c4*4+3][r] = v.w;
        }
        __syncthreads();

        #pragma unroll
        for (int k = 0; k < 16; k++) {
            float a0 = As[k][ty * 2];
            float a1 = As[k][ty * 2 + 1];
            float4 b = *reinterpret_cast<const float4*>(&Bs[k][tx * 4]);
            float bv[4] = {b.x, b.y, b.z, b.w};
            #pragma unroll
            for (int j = 0; j < 4; j++) {
                acc[0][j] = fmaf(a0, bv[j], acc[0][j]);
                acc[1][j] = fmaf(a1, bv[j], acc[1][j]);
            }
        }
        __syncthreads();
    }

    float4 b4 = *reinterpret_cast<const float4*>(bias + n0 + tx * 4);
    #pragma unroll
    for (int i = 0; i < 2; i++) {
        int m = m0 + ty * 2 + i;
        size_t off = (size_t)m * D + n0 + tx * 4;
        float4 v = make_float4(__fadd_rn(acc[i][0], b4.x),
                               __fadd_rn(acc[i][1], b4.y),
                               __fadd_rn(acc[i][2], b4.z),
                               __fadd_rn(acc[i][3], b4.w));
        *reinterpret_cast<float4*>(C + off) = v;
    }
}

// ---------------- GRU gate (float4, separate hin/hout) ---------------------
__global__ void gru_gate_kernel(const float* __restrict__ gi,
                                const float* __restrict__ gh,
                                const float* __restrict__ hin,
                                float* __restrict__ hout)
{
    int q = blockIdx.x * blockDim.x + threadIdx.x;   // over B*H/4
    int b = q >> 8;
    int j4 = (q & 255) << 2;
    size_t base = (size_t)b * G3H + j4;
    size_t hoff = (size_t)b * H + j4;

    float4 ir4 = *reinterpret_cast<const float4*>(gi + base);
    float4 iz4 = *reinterpret_cast<const float4*>(gi + base + H);
    float4 in4 = *reinterpret_cast<const float4*>(gi + base + 2 * H);
    float4 hr4 = *reinterpret_cast<const float4*>(gh + base);
    float4 hz4 = *reinterpret_cast<const float4*>(gh + base + H);
    float4 hn4 = *reinterpret_cast<const float4*>(gh + base + 2 * H);
    float4 hp4 = *reinterpret_cast<const float4*>(hin + hoff);

    float hv[4];
    const float ir[4] = {ir4.x, ir4.y, ir4.z, ir4.w};
    const float iz[4] = {iz4.x, iz4.y, iz4.z, iz4.w};
    const float in_[4] = {in4.x, in4.y, in4.z, in4.w};
    const float hr[4] = {hr4.x, hr4.y, hr4.z, hr4.w};
    const float hz[4] = {hz4.x, hz4.y, hz4.z, hz4.w};
    const float hn[4] = {hn4.x, hn4.y, hn4.z, hn4.w};
    const float hp[4] = {hp4.x, hp4.y, hp4.z, hp4.w};

    #pragma unroll
    for (int e = 0; e < 4; e++) {
        float sr = __fadd_rn(ir[e], hr[e]);
        float sz = __fadd_rn(iz[e], hz[e]);
        float r  = __fdiv_rn(1.f, __fadd_rn(1.f, expf(-sr)));
        float zg = __fdiv_rn(1.f, __fadd_rn(1.f, expf(-sz)));
        float n  = tanhf(__fadd_rn(in_[e], __fmul_rn(r, hn[e])));
        hv[e] = __fadd_rn(__fmul_rn(__fsub_rn(1.f, zg), n),
                          __fmul_rn(zg, hp[e]));
    }
    *reinterpret_cast<float4*>(hout + hoff) =
        make_float4(hv[0], hv[1], hv[2], hv[3]);
}

// ---------------- paired log-softmax + argmax + one-hot --------------------
__global__ void softmax_kernel(const float* __restrict__ tmp,
                               float* __restrict__ inp,
                               float* __restrict__ dout, int t)
{
    int i = blockIdx.x * blockDim.x + threadIdx.x;
    int b = i >> 7;
    int f = i & 127;
    float a = tmp[(size_t)b * D + f];
    float c = tmp[(size_t)b * D + 128 + f];
    float m  = fmaxf(a, c);
    float sa = __fsub_rn(a, m);
    float sc = __fsub_rn(c, m);
    float lse = logf(__fadd_rn(expf(sa), expf(sc)));
    float la = __fsub_rn(sa, lse);
    float lc = __fsub_rn(sc, lse);
    size_t ob = (size_t)b * NSTEP * D + (size_t)t * D;
    dout[ob + f]       = la;
    dout[ob + 128 + f] = lc;
    int idx = (la >= lc) ? 0 : 1;
    inp[(size_t)b * KIN + 2 * f]     = (idx == 0) ? 1.f : 0.f;
    inp[(size_t)b * KIN + 2 * f + 1] = (idx == 1) ? 1.f : 0.f;
}

__global__ void init_inp_kernel(const float* __restrict__ z,
                                float* __restrict__ inp)
{
    int i = blockIdx.x * blockDim.x + threadIdx.x;
    int b = i >> 9;
    int j = i & (KIN - 1);
    float v;
    if (j < D) v = (j == D - 1) ? 1.f : 0.f;
    else       v = z[(size_t)b * L + (j - D)];
    inp[i] = v;
}

// ---------------- launch ---------------------------------------------------
extern "C" void kernel_launch(void* const* d_in, const int* in_sizes, int n_in,
                              void* d_out, int out_size)
{
    (void)in_sizes; (void)n_in; (void)out_size;
    const float* z      = (const float*)d_in[0];
    const float* W_init = (const float*)d_in[1];
    const float* b_init = (const float*)d_in[2];
    const float* W_ih1  = (const float*)d_in[3];
    const float* W_hh1  = (const float*)d_in[4];
    const float* b_ih1  = (const float*)d_in[5];
    const float* b_hh1  = (const float*)d_in[6];
    const float* W_ih2  = (const float*)d_in[7];
    const float* W_hh2  = (const float*)d_in[8];
    const float* b_ih2  = (const float*)d_in[9];
    const float* b_hh2  = (const float*)d_in[10];
    const float* W_out  = (const float*)d_in[11];
    const float* b_out  = (const float*)d_in[12];
    float* out = (float*)d_out;

    float *inp, *gi1, *gh1, *gi2, *gh2, *h1, *h2, *tb;
    cudaGetSymbolAddress((void**)&inp, g_inp);
    cudaGetSymbolAddress((void**)&gi1, g_gi1);
    cudaGetSymbolAddress((void**)&gh1, g_gh1);
    cudaGetSymbolAddress((void**)&gi2, g_gi2);
    cudaGetSymbolAddress((void**)&gh2, g_gh2);
    cudaGetSymbolAddress((void**)&h1,  g_h1);
    cudaGetSymbolAddress((void**)&h2,  g_h2);
    cudaGetSymbolAddress((void**)&tb,  g_tmp);

    // side stream + events (created fresh each call; host-side resources only)
    cudaStream_t P;
    cudaStreamCreateWithFlags(&P, cudaStreamNonBlocking);
    cudaEvent_t ev0, ev_gh1[NSTEP], ev_gh2[NSTEP], ev_h1[NSTEP], ev_h2[NSTEP];
    cudaEventCreateWithFlags(&ev0, cudaEventDisableTiming);
    for (int t = 0; t < NSTEP; t++) {
        cudaEventCreateWithFlags(&ev_gh1[t], cudaEventDisableTiming);
        cudaEventCreateWithFlags(&ev_gh2[t], cudaEventDisableTiming);
        cudaEventCreateWithFlags(&ev_h1[t],  cudaEventDisableTiming);
        cudaEventCreateWithFlags(&ev_h2[t],  cudaEventDisableTiming);
    }

    const dim3 blk(256);
    const dim3 grid3h(G3H / BN, B / BM);          // 24 x 16 = 384
    const dim3 grid_h(H / SBN, B / SBM);
    const dim3 grid_wout(D / WBN, B / WBM);       // 4 x 64 = 256
    const int  gate_blocks = (B * H / 4) / 256;
    const int  sm_blocks   = (B * 128) / 256;

    // Prologue (stream M = null): inp, h1_init
    init_inp_kernel<<<(B * KIN) / 256, blk>>>(z, inp);
    gemm_kernel<1><<<grid_h, blk>>>(z, L, W_init, L, b_init, h1, H, L);
    cudaEventRecord(ev0, 0);
    // P: gh1(0) = h1_init @ W_hh1
    cudaStreamWaitEvent(P, ev0, 0);
    gemm3h_kernel<<<grid3h, blk, 0, P>>>(h1, H, W_hh1, H, b_hh1, gh1, H);
    cudaEventRecord(ev_gh1[0], P);

    for (int t = 0; t < NSTEP; t++) {
        // M: gi1(t) = inp @ W_ih1^T + b_ih1
        gemm3h_kernel<<<grid3h, blk>>>(inp, KIN, W_ih1, KIN, b_ih1, gi1, KIN);
        // M: gate1(t)  (needs gh1(t) from P)
        cudaStreamWaitEvent(0, ev_gh1[t], 0);
        gru_gate_kernel<<<gate_blocks, blk>>>(gi1, gh1, h1, h1);
        cudaEventRecord(ev_h1[t], 0);
        // P: gh1(t+1) = h1(t) @ W_hh1  (overlaps with M's gi2/gate2/wout)
        if (t + 1 < NSTEP) {
            cudaStreamWaitEvent(P, ev_h1[t], 0);
            gemm3h_kernel<<<grid3h, blk, 0, P>>>(h1, H, W_hh1, H, b_hh1,
                                                 gh1, H);
            cudaEventRecord(ev_gh1[t + 1], P);
        }
        // gh2(t): t=0 depends on gate1(0) (h2_prev = h1(0)); run in M.
        if (t == 0)
            gemm3h_kernel<<<grid3h, blk>>>(h1, H, W_hh2, H, b_hh2, gh2, H);
        // M: gi2(t) = h1(t) @ W_ih2
        gemm3h_kernel<<<grid3h, blk>>>(h1, H, W_ih2, H, b_ih2, gi2, H);
        // M: gate2(t)  (needs gh2(t); t>=1 from P)
        if (t > 0) cudaStreamWaitEvent(0, ev_gh2[t], 0);
        gru_gate_kernel<<<gate_blocks, blk>>>(gi2, gh2,
                                              (t == 0) ? h1 : h2, h2);
        cudaEventRecord(ev_h2[t], 0);
        // P: gh2(t+1) = h2(t) @ W_hh2  (overlaps with M's wout/softmax/gi1)
        if (t + 1 < NSTEP) {
            cudaStreamWaitEvent(P, ev_h2[t], 0);
            gemm3h_kernel<<<grid3h, blk, 0, P>>>(h2, H, W_hh2, H, b_hh2,
                                                 gh2, H);
            cudaEventRecord(ev_gh2[t + 1], P);
        }
        // M: logits + softmax
        gemm_wout_kernel<<<grid_wout, blk>>>(h2, W_out, b_out, tb);
        softmax_kernel<<<sm_blocks, blk>>>(tb, inp, out, t);
    }
    // P is joined: its last events (ev_gh1/gh2[63]) were waited in M at t=63.
}

// round 16
// speedup vs baseline: 1.1545x; 1.0613x over previous
#include <cuda_runtime.h>
#include <math.h>

// R15 = R14 resubmission (R14 bench was an infra failure; FFMA2 untested).
// R13 two-stream structure; gemm3h inner loop uses packed fma.rn.f32x2
// (FFMA2) over adjacent n-column pairs. Per-output chains are lane-exact
// vs the scalar version (same RN FMA per lane, same ascending-k order).
// Epilogue cleaned (dead scaffolding removed; live ops identical).

#define B     2048
#define L     256
#define H     1024
#define D     256
#define NSTEP 64
#define G3H   (3*H)   // 3072
#define KIN   (D + L) // 512

// ---------------- scratch (device globals: allocation-free) ----------------
__device__ float g_inp [(size_t)B * KIN];
__device__ float g_gi1 [(size_t)B * G3H];
__device__ float g_gh1 [(size_t)B * G3H];
__device__ float g_gi2 [(size_t)B * G3H];
__device__ float g_gh2 [(size_t)B * G3H];
__device__ float g_h1  [(size_t)B * H];
__device__ float g_h2  [(size_t)B * H];
__device__ float g_tmp [(size_t)B * D];

// ============ 128x128 GEMM: C[B,G3H] = A @ W^T + bias, FFMA2 inner =========
#define BM 128
#define BN 128
#define NT 256

__global__ void __launch_bounds__(NT, 2) gemm3h_kernel(
    const float* __restrict__ A, int lda,
    const float* __restrict__ W, int ldw,
    const float* __restrict__ bias,
    float* __restrict__ C, int K)
{
    __shared__ float As[2][16][BM + 4];
    __shared__ float Bs[2][16][BN + 4];

    const int tid = threadIdx.x;
    const int tx  = tid & 15;
    const int ty  = tid >> 4;
    const int m0  = blockIdx.y * BM;
    const int n0  = blockIdx.x * BN;
    const int r0  = tid >> 2;
    const int c4  = tid & 3;

    const float* Ap = A + (size_t)(m0 + r0) * lda + c4 * 4;
    const float* Wp = W + (size_t)(n0 + r0) * ldw + c4 * 4;

    // acc2[i][j] packs outputs (i, 2j) and (i, 2j+1): lane-exact scalar chains
    unsigned long long acc2[8][4];
    #pragma unroll
    for (int i = 0; i < 8; i++)
        #pragma unroll
        for (int j = 0; j < 4; j++) acc2[i][j] = 0ull;

    float4 pa[2], pb[2];
    int cur = 0;

    auto fetchA = [&](int kt) {
        pa[0] = *reinterpret_cast<const float4*>(Ap + kt);
        pa[1] = *reinterpret_cast<const float4*>(Ap + (size_t)64 * lda + kt);
    };
    auto fetchB = [&](int kt) {
        pb[0] = *reinterpret_cast<const float4*>(Wp + kt);
        pb[1] = *reinterpret_cast<const float4*>(Wp + (size_t)64 * ldw + kt);
    };
    auto storeA = [&](int buf) {
        As[buf][c4*4+0][r0] = pa[0].x; As[buf][c4*4+1][r0] = pa[0].y;
        As[buf][c4*4+2][r0] = pa[0].z; As[buf][c4*4+3][r0] = pa[0].w;
        As[buf][c4*4+0][r0+64] = pa[1].x; As[buf][c4*4+1][r0+64] = pa[1].y;
        As[buf][c4*4+2][r0+64] = pa[1].z; As[buf][c4*4+3][r0+64] = pa[1].w;
    };
    auto storeB = [&](int buf) {
        Bs[buf][c4*4+0][r0] = pb[0].x; Bs[buf][c4*4+1][r0] = pb[0].y;
        Bs[buf][c4*4+2][r0] = pb[0].z; Bs[buf][c4*4+3][r0] = pb[0].w;
        Bs[buf][c4*4+0][r0+64] = pb[1].x; Bs[buf][c4*4+1][r0+64] = pb[1].y;
        Bs[buf][c4*4+2][r0+64] = pb[1].z; Bs[buf][c4*4+3][r0+64] = pb[1].w;
    };

    float a_fr[2][8];
    unsigned long long b2_fr[2][4];
    auto load_frag = [&](int k, int s) {
        float4 a0 = *reinterpret_cast<const float4*>(&As[cur][k][ty * 4]);
        float4 a1 = *reinterpret_cast<const float4*>(&As[cur][k][64 + ty * 4]);
        float4 b0 = *reinterpret_cast<const float4*>(&Bs[cur][k][tx * 4]);
        float4 b1 = *reinterpret_cast<const float4*>(&Bs[cur][k][64 + tx * 4]);
        a_fr[s][0]=a0.x; a_fr[s][1]=a0.y; a_fr[s][2]=a0.z; a_fr[s][3]=a0.w;
        a_fr[s][4]=a1.x; a_fr[s][5]=a1.y; a_fr[s][6]=a1.z; a_fr[s][7]=a1.w;
        asm("mov.b64 %0, {%1, %2};" : "=l"(b2_fr[s][0]) : "f"(b0.x), "f"(b0.y));
        asm("mov.b64 %0, {%1, %2};" : "=l"(b2_fr[s][1]) : "f"(b0.z), "f"(b0.w));
        asm("mov.b64 %0, {%1, %2};" : "=l"(b2_fr[s][2]) : "f"(b1.x), "f"(b1.y));
        asm("mov.b64 %0, {%1, %2};" : "=l"(b2_fr[s][3]) : "f"(b1.z), "f"(b1.w));
    };

    const int ntiles = K / 16;
    fetchA(0); fetchB(0);
    storeA(0); storeB(0);
    __syncthreads();

    for (int t = 0; t < ntiles; t++) {
        const bool hn = (t + 1 < ntiles);
        if (hn) { fetchA((t + 1) * 16); fetchB((t + 1) * 16); }

        load_frag(0, 0);
        #pragma unroll
        for (int k = 0; k < 16; k++) {
            const int s = k & 1;
            if (k + 1 < 16) load_frag(k + 1, s ^ 1);
            if (k == 9  && hn) storeA(cur ^ 1);
            if (k == 13 && hn) storeB(cur ^ 1);
            #pragma unroll
            for (int i = 0; i < 8; i++) {
                unsigned long long a2;
                asm("mov.b64 %0, {%1, %1};" : "=l"(a2) : "f"(a_fr[s][i]));
                #pragma unroll
                for (int j = 0; j < 4; j++)
                    asm("fma.rn.f32x2 %0, %1, %2, %0;"
                        : "+l"(acc2[i][j]) : "l"(a2), "l"(b2_fr[s][j]));
            }
        }
        __syncthreads();
        if (hn) cur ^= 1;
    }

    // Epilogue: unpack packed accumulators, bias after full K sum.
    float4 bb0 = *reinterpret_cast<const float4*>(bias + n0 + tx * 4);
    float4 bb1 = *reinterpret_cast<const float4*>(bias + n0 + 64 + tx * 4);
    const float bb[8] = {bb0.x, bb0.y, bb0.z, bb0.w, bb1.x, bb1.y, bb1.z, bb1.w};

    #pragma unroll
    for (int i = 0; i < 8; i++) {
        int m = m0 + ((i < 4) ? (ty * 4 + i) : (64 + ty * 4 + (i - 4)));
        size_t off = (size_t)m * G3H + n0;
        float q[8];
        #pragma unroll
        for (int j = 0; j < 4; j++) {
            float lo, hi;
            asm("mov.b64 {%0, %1}, %2;" : "=f"(lo), "=f"(hi) : "l"(acc2[i][j]));
            q[2*j]   = __fadd_rn(lo, bb[2*j]);
            q[2*j+1] = __fadd_rn(hi, bb[2*j+1]);
        }
        *reinterpret_cast<float4*>(C + off + tx * 4) =
            make_float4(q[0], q[1], q[2], q[3]);
        *reinterpret_cast<float4*>(C + off + 64 + tx * 4) =
            make_float4(q[4], q[5], q[6], q[7]);
    }
}

// ============ small GEMM (prologue h1 init) ================================
#define SBM 128
#define SBN 64

template<int ACT>
__global__ void __launch_bounds__(256, 4) gemm_kernel(
    const float* __restrict__ A, int lda,
    const float* __restrict__ W, int ldw,
    const float* __restrict__ bias,
    float* __restrict__ C,
    int N, int K)
{
    __shared__ float As[16][SBM + 4];
    __shared__ float Bs[16][SBN + 4];

    const int tid = threadIdx.x;
    const int tx  = tid & 15;
    const int ty  = tid >> 4;
    const int m0  = blockIdx.y * SBM;
    const int n0  = blockIdx.x * SBN;

    float acc[8][4];
    #pragma unroll
    for (int i = 0; i < 8; i++)
        #pragma unroll
        for (int j = 0; j < 4; j++) acc[i][j] = 0.f;

    for (int kt = 0; kt < K; kt += 16) {
        #pragma unroll
        for (int l = 0; l < 2; l++) {
            int idx4 = tid + l * 256;
            int r = idx4 >> 2, c4 = idx4 & 3;
            float4 v = *reinterpret_cast<const float4*>(
                A + (size_t)(m0 + r) * lda + kt + c4 * 4);
            As[c4*4+0][r] = v.x; As[c4*4+1][r] = v.y;
            As[c4*4+2][r] = v.z; As[c4*4+3][r] = v.w;
        }
        {
            int r = tid >> 2, c4 = tid & 3;
            float4 v = *reinterpret_cast<const float4*>(
                W + (size_t)(n0 + r) * ldw + kt + c4 * 4);
            Bs[c4*4+0][r] = v.x; Bs[c4*4+1][r] = v.y;
            Bs[c4*4+2][r] = v.z; Bs[c4*4+3][r] = v.w;
        }
        __syncthreads();

        #pragma unroll
        for (int k = 0; k < 16; k++) {
            float4 a0 = *reinterpret_cast<const float4*>(&As[k][ty * 8]);
            float4 a1 = *reinterpret_cast<const float4*>(&As[k][ty * 8 + 4]);
            float4 b0 = *reinterpret_cast<const float4*>(&Bs[k][tx * 4]);
            float av[8] = {a0.x, a0.y, a0.z, a0.w, a1.x, a1.y, a1.z, a1.w};
            float bv[4] = {b0.x, b0.y, b0.z, b0.w};
            #pragma unroll
            for (int i = 0; i < 8; i++)
                #pragma unroll
                for (int j = 0; j < 4; j++)
                    acc[i][j] = fmaf(av[i], bv[j], acc[i][j]);
        }
        __syncthreads();
    }

    float4 b4 = make_float4(0.f, 0.f, 0.f, 0.f);
    if (bias) b4 = *reinterpret_cast<const float4*>(bias + n0 + tx * 4);

    #pragma unroll
    for (int i = 0; i < 8; i++) {
        int m = m0 + ty * 8 + i;
        size_t off = (size_t)m * N + n0 + tx * 4;
        float4 v = make_float4(__fadd_rn(acc[i][0], b4.x),
                               __fadd_rn(acc[i][1], b4.y),
                               __fadd_rn(acc[i][2], b4.z),
                               __fadd_rn(acc[i][3], b4.w));
        if (ACT == 1) {
            v.x = tanhf(v.x); v.y = tanhf(v.y);
            v.z = tanhf(v.z); v.w = tanhf(v.w);
        }
        *reinterpret_cast<float4*>(C + off) = v;
    }
}

// ============ W_out GEMM: 32x64 tiles ======================================
#define WBM 32
#define WBN 64

__global__ void __launch_bounds__(256, 4) gemm_wout_kernel(
    const float* __restrict__ A,
    const float* __restrict__ W,
    const float* __restrict__ bias,
    float* __restrict__ C)
{
    __shared__ float As[16][WBM + 4];
    __shared__ float Bs[16][WBN + 4];

    const int tid = threadIdx.x;
    const int tx  = tid & 15;
    const int ty  = tid >> 4;
    const int m0  = blockIdx.y * WBM;
    const int n0  = blockIdx.x * WBN;

    float acc[2][4];
    #pragma unroll
    for (int i = 0; i < 2; i++)
        #pragma unroll
        for (int j = 0; j < 4; j++) acc[i][j] = 0.f;

    for (int kt = 0; kt < H; kt += 16) {
        if (tid < 128) {
            int r = tid >> 2, c4 = tid & 3;
            float4 v = *reinterpret_cast<const float4*>(
                A + (size_t)(m0 + r) * H + kt + c4 * 4);
            As[c4*4+0][r] = v.x; As[c4*4+1][r] = v.y;
            As[c4*4+2][r] = v.z; As[c4*4+3][r] = v.w;
        }
        {
            int r = tid >> 2, c4 = tid & 3;
            float4 v = *reinterpret_cast<const float4*>(
                W + (size_t)(n0 + r) * H + kt + c4 * 4);
            Bs[c4*4+0][r] = v.x; Bs[c4*4+1][r] = v.y;
            Bs[c4*4+2][r] = v.z; Bs[c4*4+3][r] = v.w;
        }
        __syncthreads();

        #pragma unroll
        for (int k = 0; k < 16; k++) {
            float a0 = As[k][ty * 2];
            float a1 = As[k][ty * 2 + 1];
            float4 b = *reinterpret_cast<const float4*>(&Bs[k][tx * 4]);
            float bv[4] = {b.x, b.y, b.z, b.w};
            #pragma unroll
            for (int j = 0; j < 4; j++) {
                acc[0][j] = fmaf(a0, bv[j], acc[0][j]);
                acc[1][j] = fmaf(a1, bv[j], acc[1][j]);
            }
        }
        __syncthreads();
    }

    float4 b4 = *reinterpret_cast<const float4*>(bias + n0 + tx * 4);
    #pragma unroll
    for (int i = 0; i < 2; i++) {
        int m = m0 + ty * 2 + i;
        size_t off = (size_t)m * D + n0 + tx * 4;
        float4 v = make_float4(__fadd_rn(acc[i][0], b4.x),
                               __fadd_rn(acc[i][1], b4.y),
                               __fadd_rn(acc[i][2], b4.z),
                               __fadd_rn(acc[i][3], b4.w));
        *reinterpret_cast<float4*>(C + off) = v;
    }
}

// ---------------- GRU gate (float4, separate hin/hout) ---------------------
__global__ void gru_gate_kernel(const float* __restrict__ gi,
                                const float* __restrict__ gh,
                                const float* __restrict__ hin,
                                float* __restrict__ hout)
{
    int q = blockIdx.x * blockDim.x + threadIdx.x;
    int b = q >> 8;
    int j4 = (q & 255) << 2;
    size_t base = (size_t)b * G3H + j4;
    size_t hoff = (size_t)b * H + j4;

    float4 ir4 = *reinterpret_cast<const float4*>(gi + base);
    float4 iz4 = *reinterpret_cast<const float4*>(gi + base + H);
    float4 in4 = *reinterpret_cast<const float4*>(gi + base + 2 * H);
    float4 hr4 = *reinterpret_cast<const float4*>(gh + base);
    float4 hz4 = *reinterpret_cast<const float4*>(gh + base + H);
    float4 hn4 = *reinterpret_cast<const float4*>(gh + base + 2 * H);
    float4 hp4 = *reinterpret_cast<const float4*>(hin + hoff);

    float hv[4];
    const float ir[4] = {ir4.x, ir4.y, ir4.z, ir4.w};
    const float iz[4] = {iz4.x, iz4.y, iz4.z, iz4.w};
    const float in_[4] = {in4.x, in4.y, in4.z, in4.w};
    const float hr[4] = {hr4.x, hr4.y, hr4.z, hr4.w};
    const float hz[4] = {hz4.x, hz4.y, hz4.z, hz4.w};
    const float hn[4] = {hn4.x, hn4.y, hn4.z, hn4.w};
    const float hp[4] = {hp4.x, hp4.y, hp4.z, hp4.w};

    #pragma unroll
    for (int e = 0; e < 4; e++) {
        float sr = __fadd_rn(ir[e], hr[e]);
        float sz = __fadd_rn(iz[e], hz[e]);
        float r  = __fdiv_rn(1.f, __fadd_rn(1.f, expf(-sr)));
        float zg = __fdiv_rn(1.f, __fadd_rn(1.f, expf(-sz)));
        float n  = tanhf(__fadd_rn(in_[e], __fmul_rn(r, hn[e])));
        hv[e] = __fadd_rn(__fmul_rn(__fsub_rn(1.f, zg), n),
                          __fmul_rn(zg, hp[e]));
    }
    *reinterpret_cast<float4*>(hout + hoff) =
        make_float4(hv[0], hv[1], hv[2], hv[3]);
}

// ---------------- paired log-softmax + argmax + one-hot --------------------
__global__ void softmax_kernel(const float* __restrict__ tmp,
                               float* __restrict__ inp,
                               float* __restrict__ dout, int t)
{
    int i = blockIdx.x * blockDim.x + threadIdx.x;
    int b = i >> 7;
    int f = i & 127;
    float a = tmp[(size_t)b * D + f];
    float c = tmp[(size_t)b * D + 128 + f];
    float m  = fmaxf(a, c);
    float sa = __fsub_rn(a, m);
    float sc = __fsub_rn(c, m);
    float lse = logf(__fadd_rn(expf(sa), expf(sc)));
    float la = __fsub_rn(sa, lse);
    float lc = __fsub_rn(sc, lse);
    size_t ob = (size_t)b * NSTEP * D + (size_t)t * D;
    dout[ob + f]       = la;
    dout[ob + 128 + f] = lc;
    int idx = (la >= lc) ? 0 : 1;
    inp[(size_t)b * KIN + 2 * f]     = (idx == 0) ? 1.f : 0.f;
    inp[(size_t)b * KIN + 2 * f + 1] = (idx == 1) ? 1.f : 0.f;
}

__global__ void init_inp_kernel(const float* __restrict__ z,
                                float* __restrict__ inp)
{
    int i = blockIdx.x * blockDim.x + threadIdx.x;
    int b = i >> 9;
    int j = i & (KIN - 1);
    float v;
    if (j < D) v = (j == D - 1) ? 1.f : 0.f;
    else       v = z[(size_t)b * L + (j - D)];
    inp[i] = v;
}

// ---------------- launch ---------------------------------------------------
extern "C" void kernel_launch(void* const* d_in, const int* in_sizes, int n_in,
                              void* d_out, int out_size)
{
    (void)in_sizes; (void)n_in; (void)out_size;
    const float* z      = (const float*)d_in[0];
    const float* W_init = (const float*)d_in[1];
    const float* b_init = (const float*)d_in[2];
    const float* W_ih1  = (const float*)d_in[3];
    const float* W_hh1  = (const float*)d_in[4];
    const float* b_ih1  = (const float*)d_in[5];
    const float* b_hh1  = (const float*)d_in[6];
    const float* W_ih2  = (const float*)d_in[7];
    const float* W_hh2  = (const float*)d_in[8];
    const float* b_ih2  = (const float*)d_in[9];
    const float* b_hh2  = (const float*)d_in[10];
    const float* W_out  = (const float*)d_in[11];
    const float* b_out  = (const float*)d_in[12];
    float* out = (float*)d_out;

    float *inp, *gi1, *gh1, *gi2, *gh2, *h1, *h2, *tb;
    cudaGetSymbolAddress((void**)&inp, g_inp);
    cudaGetSymbolAddress((void**)&gi1, g_gi1);
    cudaGetSymbolAddress((void**)&gh1, g_gh1);
    cudaGetSymbolAddress((void**)&gi2, g_gi2);
    cudaGetSymbolAddress((void**)&gh2, g_gh2);
    cudaGetSymbolAddress((void**)&h1,  g_h1);
    cudaGetSymbolAddress((void**)&h2,  g_h2);
    cudaGetSymbolAddress((void**)&tb,  g_tmp);

    cudaStream_t P;
    cudaStreamCreateWithFlags(&P, cudaStreamNonBlocking);
    cudaEvent_t ev0, ev_gh1[NSTEP], ev_gh2[NSTEP], ev_h1[NSTEP], ev_h2[NSTEP];
    cudaEventCreateWithFlags(&ev0, cudaEventDisableTiming);
    for (int t = 0; t < NSTEP; t++) {
        cudaEventCreateWithFlags(&ev_gh1[t], cudaEventDisableTiming);
        cudaEventCreateWithFlags(&ev_gh2[t], cudaEventDisableTiming);
        cudaEventCreateWithFlags(&ev_h1[t],  cudaEventDisableTiming);
        cudaEventCreateWithFlags(&ev_h2[t],  cudaEventDisableTiming);
    }

    const dim3 blk(256);
    const dim3 grid3h(G3H / BN, B / BM);
    const dim3 grid_h(H / SBN, B / SBM);
    const dim3 grid_wout(D / WBN, B / WBM);
    const int  gate_blocks = (B * H / 4) / 256;
    const int  sm_blocks   = (B * 128) / 256;

    init_inp_kernel<<<(B * KIN) / 256, blk>>>(z, inp);
    gemm_kernel<1><<<grid_h, blk>>>(z, L, W_init, L, b_init, h1, H, L);
    cudaEventRecord(ev0, 0);
    cudaStreamWaitEvent(P, ev0, 0);
    gemm3h_kernel<<<grid3h, blk, 0, P>>>(h1, H, W_hh1, H, b_hh1, gh1, H);
    cudaEventRecord(ev_gh1[0], P);

    for (int t = 0; t < NSTEP; t++) {
        gemm3h_kernel<<<grid3h, blk>>>(inp, KIN, W_ih1, KIN, b_ih1, gi1, KIN);
        cudaStreamWaitEvent(0, ev_gh1[t], 0);
        gru_gate_kernel<<<gate_blocks, blk>>>(gi1, gh1, h1, h1);
        cudaEventRecord(ev_h1[t], 0);
        if (t + 1 < NSTEP) {
            cudaStreamWaitEvent(P, ev_h1[t], 0);
            gemm3h_kernel<<<grid3h, blk, 0, P>>>(h1, H, W_hh1, H, b_hh1,
                                                 gh1, H);
            cudaEventRecord(ev_gh1[t + 1], P);
        }
        if (t == 0)
            gemm3h_kernel<<<grid3h, blk>>>(h1, H, W_hh2, H, b_hh2, gh2, H);
        gemm3h_kernel<<<grid3h, blk>>>(h1, H, W_ih2, H, b_ih2, gi2, H);
        if (t > 0) cudaStreamWaitEvent(0, ev_gh2[t], 0);
        gru_gate_kernel<<<gate_blocks, blk>>>(gi2, gh2,
                                              (t == 0) ? h1 : h2, h2);
        cudaEventRecord(ev_h2[t], 0);
        if (t + 1 < NSTEP) {
            cudaStreamWaitEvent(P, ev_h2[t], 0);
            gemm3h_kernel<<<grid3h, blk, 0, P>>>(h2, H, W_hh2, H, b_hh2,
                                                 gh2, H);
            cudaEventRecord(ev_gh2[t + 1], P);
        }
        gemm_wout_kernel<<<grid_wout, blk>>>(h2, W_out, b_out, tb);
        softmax_kernel<<<sm_blocks, blk>>>(tb, inp, out, t);
    }
}